// round 1
// baseline (speedup 1.0000x reference)
#include <cuda_runtime.h>
#include <math.h>
#include <stdint.h>

#define N_ 8192
#define E_ 131072
#define M_ (E_ + N_)          // 139264 edges incl self loops
#define H_ 128
#define K_ 4096

// ---------------- device scratch (static allocations only) ----------------
static __device__ float g_bufA[(size_t)N_*H_];
static __device__ float g_bufB[(size_t)N_*H_];
static __device__ float g_bufC[(size_t)N_*H_];
static __device__ float g_bufT[(size_t)N_*H_];
static __device__ float g_dis[N_];
static __device__ int   g_cnt[N_];
static __device__ int   g_fill[N_];
static __device__ int   g_rowptr[N_+1];
static __device__ int   g_eidx[M_];
static __device__ float g_alpha[M_];
static __device__ float g_aq[N_];
static __device__ float g_ah[N_];
static __device__ float g_cl1[N_], g_cl2[N_], g_cl3[N_];
static __device__ float g_fit[N_];
static __device__ int   g_sel[N_];
static __device__ int   g_col[N_];
static __device__ int   g_ncol[K_];
static __device__ float g_xp[(size_t)K_*H_];
static __device__ int   g_scnt[N_];
static __device__ int   g_srowptr[N_+1];
static __device__ int   g_sk[M_];
static __device__ float g_sa[M_];
static __device__ float g_NK[(size_t)N_*K_];   // holds AS, then reused for P
static __device__ float g_Ac[(size_t)K_*K_];

// ---------------- helpers ----------------
__device__ __forceinline__ int esrc_f(const int* __restrict__ e0, int e){ return (e < E_) ? e0[e] : (e - E_); }
__device__ __forceinline__ int edst_f(const int* __restrict__ e1, int e){ return (e < E_) ? e1[e] : (e - E_); }

// ---------------- small utility kernels ----------------
__global__ void k_init0(){
    int i = blockIdx.x*blockDim.x + threadIdx.x;
    if (i < N_){ g_cnt[i]=0; g_fill[i]=0; g_scnt[i]=0; }
}
__global__ void k_zero_fill(){
    int i = blockIdx.x*blockDim.x + threadIdx.x;
    if (i < N_) g_fill[i]=0;
}
__global__ void k_zeroNK(){
    size_t i = (size_t)blockIdx.x*blockDim.x + threadIdx.x;
    size_t st = (size_t)gridDim.x*blockDim.x;
    size_t n = (size_t)N_*K_;
    for(; i<n; i+=st) g_NK[i]=0.f;
}
__global__ void k_count(const int* __restrict__ e1){
    int e = blockIdx.x*blockDim.x + threadIdx.x;
    if (e < M_) atomicAdd(&g_cnt[edst_f(e1,e)], 1);
}
__global__ void k_dis(){
    int i = blockIdx.x*blockDim.x + threadIdx.x;
    if (i < N_) g_dis[i] = rsqrtf((float)g_cnt[i]);   // deg >= 1 (self loop)
}
// exclusive scan of n<=8192 ints, single block of 1024
__global__ void k_scan(const int* __restrict__ in, int* __restrict__ out, int n){
    __shared__ int sh[1024];
    int tid = threadIdx.x;
    int per = (n + 1023)/1024;
    int base = tid*per;
    int s = 0;
    for (int q=0;q<per;q++){ int i=base+q; if(i<n) s += in[i]; }
    sh[tid]=s; __syncthreads();
    for (int o=1;o<1024;o<<=1){
        int v = (tid>=o)? sh[tid-o] : 0;
        __syncthreads();
        sh[tid]+=v;
        __syncthreads();
    }
    int excl = (tid==0)? 0 : sh[tid-1];
    for (int q=0;q<per;q++){ int i=base+q; if(i<n){ out[i]=excl; excl += in[i]; } }
    if (tid==1023) out[n] = sh[1023];
}
__global__ void k_fill(const int* __restrict__ e1){
    int e = blockIdx.x*blockDim.x + threadIdx.x;
    if (e < M_){
        int d = edst_f(e1,e);
        int pos = g_rowptr[d] + atomicAdd(&g_fill[d],1);
        g_eidx[pos]=e;
    }
}

// ---------------- 8192x128 @ 128x128 GEMM ----------------
// grid 128 blocks (64 rows each), 256 threads. acc 8 rows x 4 cols per thread.
__global__ void k_gemm(const float* __restrict__ x, const float* __restrict__ w, float* __restrict__ y){
    __shared__ __align__(16) float xs[128*64];   // [kk][r]
    int r0 = blockIdx.x*64;
    int tid = threadIdx.x;
    for (int idx=tid; idx<64*128; idx+=256){
        int r = idx >> 7;
        int kk = idx & 127;
        xs[kk*64 + r] = x[(size_t)(r0+r)*128 + kk];
    }
    __syncthreads();
    int cg = tid & 31;     // cols 4cg..4cg+3
    int rg = tid >> 5;     // rows rg*8..rg*8+7 (constant within warp -> LDS broadcast)
    float acc[8][4];
    #pragma unroll
    for(int r=0;r<8;r++){ acc[r][0]=0.f;acc[r][1]=0.f;acc[r][2]=0.f;acc[r][3]=0.f; }
    #pragma unroll 4
    for(int kk=0;kk<128;kk++){
        float4 wv = *(const float4*)(w + kk*128 + cg*4);
        float4 x0 = *(const float4*)(xs + kk*64 + rg*8);
        float4 x1 = *(const float4*)(xs + kk*64 + rg*8 + 4);
        float xv[8] = {x0.x,x0.y,x0.z,x0.w,x1.x,x1.y,x1.z,x1.w};
        #pragma unroll
        for(int r=0;r<8;r++){
            acc[r][0] += xv[r]*wv.x; acc[r][1] += xv[r]*wv.y;
            acc[r][2] += xv[r]*wv.z; acc[r][3] += xv[r]*wv.w;
        }
    }
    #pragma unroll
    for(int r=0;r<8;r++){
        float4 o = make_float4(acc[r][0],acc[r][1],acc[r][2],acc[r][3]);
        *(float4*)(y + (size_t)(r0+rg*8+r)*128 + cg*4) = o;
    }
}

// ---------------- GCN aggregation: out[d] = b + sum_in y[src]*norm ----------------
__global__ void k_aggr(const float* __restrict__ y, const float* __restrict__ b,
                       float* __restrict__ out, const int* __restrict__ e0, int dotanh){
    int d = blockIdx.x, t = threadIdx.x;
    int beg = g_rowptr[d], end = g_rowptr[d+1];
    float dd = g_dis[d], acc = 0.f;
    for (int s=beg; s<end; s++){
        int e = g_eidx[s];
        int sr = esrc_f(e0,e);
        acc += y[(size_t)sr*128 + t] * (g_dis[sr]*dd);
    }
    acc += b[t];
    if (dotanh) acc = tanhf(acc);
    out[(size_t)d*128 + t] = acc;
}

// segment max of h over in-edges
__global__ void k_segmax(const float* __restrict__ h, float* __restrict__ out, const int* __restrict__ e0){
    int d = blockIdx.x, t = threadIdx.x;
    int beg = g_rowptr[d], end = g_rowptr[d+1];
    float acc = -INFINITY;
    for (int s=beg;s<end;s++){
        int sr = esrc_f(e0, g_eidx[s]);
        acc = fmaxf(acc, h[(size_t)sr*128 + t]);
    }
    out[(size_t)d*128 + t] = acc;
}

// aq[i] = att[0:128].(xq[i]+bq), ah[i] = att[128:256].h[i]  (warp per node)
__global__ void k_dots(const float* __restrict__ xq, const float* __restrict__ h,
                       const float* __restrict__ att, const float* __restrict__ bq){
    int node = blockIdx.x*8 + (threadIdx.x>>5);
    int lane = threadIdx.x & 31;
    float s1=0.f, s2=0.f;
    for (int q=lane; q<128; q+=32){
        s1 += att[q]     * (xq[(size_t)node*128+q] + bq[q]);
        s2 += att[128+q] *  h[(size_t)node*128+q];
    }
    #pragma unroll
    for (int o=16;o;o>>=1){ s1 += __shfl_down_sync(0xffffffffu,s1,o); s2 += __shfl_down_sync(0xffffffffu,s2,o); }
    if (!lane){ g_aq[node]=s1; g_ah[node]=s2; }
}

// per-dst softmax over edges + cluster rep cx
__global__ void k_softcx(const float* __restrict__ h, float* __restrict__ cx, const int* __restrict__ e0){
    __shared__ float red[128];
    __shared__ float cache[1024];
    int d = blockIdx.x, t = threadIdx.x;
    int beg = g_rowptr[d], end = g_rowptr[d+1];
    float aqd = g_aq[d];
    // pass 1: max
    float mx = -INFINITY;
    for (int s=beg+t; s<end; s+=128){
        int e = g_eidx[s];
        float sc = aqd + g_ah[esrc_f(e0,e)];
        sc = sc > 0.f ? sc : 0.2f*sc;
        if (s-beg < 1024) cache[s-beg] = sc;
        mx = fmaxf(mx, sc);
    }
    red[t]=mx; __syncthreads();
    for (int o=64;o;o>>=1){ if(t<o) red[t]=fmaxf(red[t],red[t+o]); __syncthreads(); }
    mx = red[0]; __syncthreads();
    // pass 2: sum of exp
    float sm = 0.f;
    for (int s=beg+t; s<end; s+=128){
        float sc;
        if (s-beg < 1024) sc = cache[s-beg];
        else { int e=g_eidx[s]; sc = aqd + g_ah[esrc_f(e0,e)]; sc = sc>0.f? sc : 0.2f*sc; }
        float ee = __expf(sc - mx);
        if (s-beg < 1024) cache[s-beg] = ee;
        sm += ee;
    }
    red[t]=sm; __syncthreads();
    for (int o=64;o;o>>=1){ if(t<o) red[t]+=red[t+o]; __syncthreads(); }
    float inv = 1.f/red[0];
    // pass 3: alpha
    for (int s=beg+t; s<end; s+=128){
        int e = g_eidx[s];
        float ee;
        if (s-beg < 1024) ee = cache[s-beg];
        else { float sc = aqd + g_ah[esrc_f(e0,e)]; sc = sc>0.f? sc:0.2f*sc; ee = __expf(sc-mx); }
        float a = ee*inv;
        g_alpha[e] = a;
        if (s-beg < 1024) cache[s-beg] = a;
    }
    __syncthreads();
    // pass 4: cx[d,t] = sum alpha*h[src,t]
    float acc = 0.f;
    for (int s=beg; s<end; s++){
        int e = g_eidx[s];
        float a = (s-beg < 1024) ? cache[s-beg] : g_alpha[e];
        acc += a * h[(size_t)esrc_f(e0,e)*128 + t];
    }
    cx[(size_t)d*128 + t] = acc;
}

// LEConv dots (warp per node)
__global__ void k_le(const float* __restrict__ cx, const float* __restrict__ lw1,
                     const float* __restrict__ lw2, const float* __restrict__ lw3){
    int node = blockIdx.x*8 + (threadIdx.x>>5);
    int lane = threadIdx.x & 31;
    float s1=0.f,s2=0.f,s3=0.f;
    for (int q=lane;q<128;q+=32){
        float v = cx[(size_t)node*128+q];
        s1 += v*lw1[q]; s2 += v*lw2[q]; s3 += v*lw3[q];
    }
    #pragma unroll
    for (int o=16;o;o>>=1){
        s1 += __shfl_down_sync(0xffffffffu,s1,o);
        s2 += __shfl_down_sync(0xffffffffu,s2,o);
        s3 += __shfl_down_sync(0xffffffffu,s3,o);
    }
    if (!lane){ g_cl1[node]=s1; g_cl2[node]=s2; g_cl3[node]=s3; }
}
__global__ void k_fit(const float* __restrict__ lb1, const int* __restrict__ e0){
    int d = blockIdx.x*blockDim.x + threadIdx.x;
    if (d >= N_) return;
    int beg=g_rowptr[d], end=g_rowptr[d+1];
    float s = 0.f;
    for (int q=beg;q<end;q++) s += g_cl3[esrc_f(e0, g_eidx[q])];
    float aggr = (float)(end-beg)*g_cl2[d] - s;
    float z = g_cl1[d] + lb1[0] + aggr;
    g_fit[d] = 1.f/(1.f + __expf(-z));
}

// top-K selection (radix select + tie-break by lowest index) + column assignment
__global__ void k_topk(){
    __shared__ int red[1024];
    __shared__ unsigned s_pref;
    __shared__ int s_need;
    int tid = threadIdx.x;
    unsigned keys[8];
    #pragma unroll
    for (int q=0;q<8;q++){
        unsigned u = __float_as_uint(g_fit[tid*8+q]);
        keys[q] = (u & 0x80000000u) ? ~u : (u | 0x80000000u);
    }
    if (tid==0){ s_pref=0u; s_need=K_; }
    __syncthreads();
    for (int b=31;b>=0;b--){
        unsigned himask = ~((1u<<b) - 1u);
        unsigned test = s_pref | (1u<<b);
        int c=0;
        #pragma unroll
        for (int q=0;q<8;q++) if ((keys[q]&himask)==test) c++;
        red[tid]=c; __syncthreads();
        for (int o=512;o;o>>=1){ if(tid<o) red[tid]+=red[tid+o]; __syncthreads(); }
        if (tid==0){ if (red[0] >= s_need) s_pref = test; else s_need -= red[0]; }
        __syncthreads();
    }
    unsigned thr = s_pref; int need = s_need;
    // rank among equal keys (index order)
    int ls=0;
    #pragma unroll
    for (int q=0;q<8;q++) ls += (keys[q]==thr);
    red[tid]=ls; __syncthreads();
    for (int o=1;o<1024;o<<=1){ int v=(tid>=o)?red[tid-o]:0; __syncthreads(); red[tid]+=v; __syncthreads(); }
    int rank = (tid? red[tid-1] : 0);
    int lsel[8];
    #pragma unroll
    for (int q=0;q<8;q++){
        bool eq = (keys[q]==thr);
        lsel[q] = (keys[q]>thr) || (eq && rank < need);
        if (eq) rank++;
        g_sel[tid*8+q] = lsel[q];
    }
    __syncthreads();
    ls=0;
    #pragma unroll
    for (int q=0;q<8;q++) ls += lsel[q];
    red[tid]=ls; __syncthreads();
    for (int o=1;o<1024;o<<=1){ int v=(tid>=o)?red[tid-o]:0; __syncthreads(); red[tid]+=v; __syncthreads(); }
    int base = (tid? red[tid-1] : 0);
    #pragma unroll
    for (int q=0;q<8;q++){
        int i = tid*8+q;
        if (lsel[q]){ g_col[i]=base; g_ncol[base]=i; base++; }
        else g_col[i]=-1;
    }
}

__global__ void k_xp(const float* __restrict__ cx){
    int i = blockIdx.x, t = threadIdx.x;
    if (!g_sel[i]) return;
    g_xp[(size_t)g_col[i]*128 + t] = cx[(size_t)i*128 + t] * g_fit[i];
}

// S (row-CSR by source) build
__global__ void k_scount(const int* __restrict__ e0, const int* __restrict__ e1){
    int e = blockIdx.x*blockDim.x + threadIdx.x;
    if (e < M_){
        int d = edst_f(e1,e);
        if (g_sel[d]) atomicAdd(&g_scnt[esrc_f(e0,e)], 1);
    }
}
__global__ void k_sfill(const int* __restrict__ e0, const int* __restrict__ e1){
    int e = blockIdx.x*blockDim.x + threadIdx.x;
    if (e < M_){
        int d = edst_f(e1,e);
        if (g_sel[d]){
            int s = esrc_f(e0,e);
            int pos = g_srowptr[s] + atomicAdd(&g_fill[s],1);
            g_sk[pos] = g_col[d];
            g_sa[pos] = g_alpha[e];
        }
    }
}

// AS[s,:] += S_row(d) for every edge (s,d)
__global__ void k_AS(const int* __restrict__ e0, const int* __restrict__ e1){
    int e = blockIdx.x*blockDim.x + threadIdx.x;
    if (e >= M_) return;
    int s = esrc_f(e0,e), d = edst_f(e1,e);
    size_t rb = (size_t)s*K_;
    int qb = g_srowptr[d], qe = g_srowptr[d+1];
    for (int q=qb;q<qe;q++) atomicAdd(&g_NK[rb + g_sk[q]], g_sa[q]);
}

// Ac[k,:] = sum over in-edges e of d=node_of_col[k]: alpha[e]*AS[src(e),:]
__global__ void k_Ac(const int* __restrict__ e0){
    int k = blockIdx.x, t = threadIdx.x;
    int d = g_ncol[k];
    float acc[16];
    #pragma unroll
    for (int c=0;c<16;c++) acc[c]=0.f;
    for (int q=g_rowptr[d]; q<g_rowptr[d+1]; q++){
        int e = g_eidx[q];
        float a = g_alpha[e];
        const float* row = &g_NK[(size_t)esrc_f(e0,e)*K_];
        #pragma unroll
        for (int c=0;c<16;c++) acc[c] += a*row[t + c*256];
    }
    float* orow = &g_Ac[(size_t)k*K_];
    #pragma unroll
    for (int c=0;c<16;c++) orow[t + c*256] = acc[c];
}

// P[i,:] = sum over S row i: alpha*Ac[k,:]   (overwrites g_NK)
__global__ void k_P(){
    int i = blockIdx.x, t = threadIdx.x;
    float acc[16];
    #pragma unroll
    for (int c=0;c<16;c++) acc[c]=0.f;
    for (int q=g_srowptr[i]; q<g_srowptr[i+1]; q++){
        const float* row = &g_Ac[(size_t)g_sk[q]*K_];
        float a = g_sa[q];
        #pragma unroll
        for (int c=0;c<16;c++) acc[c] += a*row[t + c*256];
    }
    float* orow = &g_NK[(size_t)i*K_];
    #pragma unroll
    for (int c=0;c<16;c++) orow[t + c*256] = acc[c];
}

// adj[i,j] = sum over S row j: alpha*P[i,k] ; 8 P-rows cached in smem
__global__ void k_adj(float* __restrict__ adj){
    extern __shared__ __align__(16) float Psh[];   // [k*8 + r], 128KB
    int i0 = blockIdx.x*8, tid = threadIdx.x;
    for (int r=0;r<8;r++)
        for (int k=tid;k<K_;k+=256)
            Psh[k*8+r] = g_NK[(size_t)(i0+r)*K_ + k];
    __syncthreads();
    for (int j=tid; j<N_; j+=256){
        float a0=0,a1=0,a2=0,a3=0,a4=0,a5=0,a6=0,a7=0;
        int qb = g_srowptr[j], qe = g_srowptr[j+1];
        for (int q=qb;q<qe;q++){
            int k = g_sk[q]; float a = g_sa[q];
            float4 p0 = *(const float4*)&Psh[k*8];
            float4 p1 = *(const float4*)&Psh[k*8+4];
            a0 += a*p0.x; a1 += a*p0.y; a2 += a*p0.z; a3 += a*p0.w;
            a4 += a*p1.x; a5 += a*p1.y; a6 += a*p1.z; a7 += a*p1.w;
        }
        adj[(size_t)(i0+0)*N_ + j]=a0; adj[(size_t)(i0+1)*N_ + j]=a1;
        adj[(size_t)(i0+2)*N_ + j]=a2; adj[(size_t)(i0+3)*N_ + j]=a3;
        adj[(size_t)(i0+4)*N_ + j]=a4; adj[(size_t)(i0+5)*N_ + j]=a5;
        adj[(size_t)(i0+6)*N_ + j]=a6; adj[(size_t)(i0+7)*N_ + j]=a7;
    }
}

// x_out[i,:] = sum over S row i: alpha*xp[k,:]
__global__ void k_xout(float* __restrict__ out){
    int i = blockIdx.x, t = threadIdx.x;
    float acc = 0.f;
    for (int q=g_srowptr[i]; q<g_srowptr[i+1]; q++)
        acc += g_sa[q] * g_xp[(size_t)g_sk[q]*128 + t];
    out[(size_t)i*128 + t] = acc;
}

// ---------------- host ----------------
extern "C" void kernel_launch(void* const* d_in, const int* in_sizes, int n_in,
                              void* d_out, int out_size){
    const float* nodes = (const float*)d_in[0];
    const int*   edges = (const int*)d_in[1];
    const int* e0 = edges;
    const int* e1 = edges + E_;
    const float* w1 = (const float*)d_in[3];  const float* b1 = (const float*)d_in[4];
    const float* w2 = (const float*)d_in[5];  const float* b2 = (const float*)d_in[6];
    const float* w3 = (const float*)d_in[7];  const float* b3 = (const float*)d_in[8];
    const float* w4 = (const float*)d_in[9];  const float* b4 = (const float*)d_in[10];
    const float* w5 = (const float*)d_in[11]; const float* b5 = (const float*)d_in[12];
    const float* wq = (const float*)d_in[13]; const float* bq = (const float*)d_in[14];
    const float* att = (const float*)d_in[15];
    const float* lw1 = (const float*)d_in[16]; const float* lb1 = (const float*)d_in[17];
    const float* lw2 = (const float*)d_in[18]; const float* lw3 = (const float*)d_in[19];

    float* out = (float*)d_out;
    float* x2out = out;
    float* adj  = out + (size_t)N_*H_;

    float *A,*B,*C,*T; int *cnt,*rowptr,*scnt,*srowptr;
    cudaGetSymbolAddress((void**)&A, g_bufA);
    cudaGetSymbolAddress((void**)&B, g_bufB);
    cudaGetSymbolAddress((void**)&C, g_bufC);
    cudaGetSymbolAddress((void**)&T, g_bufT);
    cudaGetSymbolAddress((void**)&cnt, g_cnt);
    cudaGetSymbolAddress((void**)&rowptr, g_rowptr);
    cudaGetSymbolAddress((void**)&scnt, g_scnt);
    cudaGetSymbolAddress((void**)&srowptr, g_srowptr);

    const int TB = 256;
    const int MB = (M_ + TB - 1)/TB;

    // graph prep
    k_init0<<<(N_+TB-1)/TB, TB>>>();
    k_count<<<MB, TB>>>(e1);
    k_dis<<<(N_+TB-1)/TB, TB>>>();
    k_scan<<<1,1024>>>(cnt, rowptr, N_);
    k_fill<<<MB, TB>>>(e1);

    // encoder
    k_gemm<<<128,256>>>(nodes, w1, T);
    k_aggr<<<N_,128>>>(T, b1, A, e0, 1);
    k_gemm<<<128,256>>>(A, w2, T);
    k_aggr<<<N_,128>>>(T, b2, B, e0, 1);     // B = h

    // pooling
    k_segmax<<<N_,128>>>(B, A, e0);          // A = neighborhood max
    k_gemm<<<128,256>>>(A, wq, T);           // T = xq (pre-bias)
    k_dots<<<N_/8,256>>>(T, B, att, bq);
    k_softcx<<<N_,128>>>(B, C, e0);          // C = cx, writes g_alpha
    k_le<<<N_/8,256>>>(C, lw1, lw2, lw3);
    k_fit<<<(N_+TB-1)/TB, TB>>>(lb1, e0);
    k_topk<<<1,1024>>>();
    k_xp<<<N_,128>>>(C);

    // S CSR by source row
    k_scount<<<MB, TB>>>(e0, e1);
    k_scan<<<1,1024>>>(scnt, srowptr, N_);
    k_zero_fill<<<(N_+TB-1)/TB, TB>>>();
    k_sfill<<<MB, TB>>>(e0, e1);

    // AS -> Ac -> P -> adj
    k_zeroNK<<<4096,256>>>();
    k_AS<<<MB, TB>>>(e0, e1);
    k_Ac<<<K_,256>>>(e0);
    k_P<<<N_,256>>>();
    cudaFuncSetAttribute(k_adj, cudaFuncAttributeMaxDynamicSharedMemorySize, 131072);
    k_adj<<<N_/8, 256, 131072>>>(adj);

    // decoder
    k_xout<<<N_,128>>>(A);                   // A = x_out
    k_gemm<<<128,256>>>(A, w3, T);
    k_aggr<<<N_,128>>>(T, b3, B, e0, 1);
    k_gemm<<<128,256>>>(B, w4, T);
    k_aggr<<<N_,128>>>(T, b4, A, e0, 1);
    k_gemm<<<128,256>>>(A, w5, T);
    k_aggr<<<N_,128>>>(T, b5, x2out, e0, 0);
}